// round 1
// baseline (speedup 1.0000x reference)
#include <cuda_runtime.h>

#define NPTS 16384
#define KCH  128

// Scratch for mixed[1], mixed[2] (concatenated-field layout, same as d_out):
// field l at offset NPTS*KCH*l*l, element (n,m,k) at off + (n*(2l+1)+m)*KCH + k
__device__ float g_m1[NPTS * 16 * KCH];
__device__ float g_m2[NPTS * 16 * KCH];

// ---------------------------------------------------------------------------
// mix kernel: for i in 0..2, l in 0..3: mixed_i[l] = density[l] @ W[i][l]
// Block = 16 points. SMEM: dens[16][16][128] (128KB) + Ws[128][128] (64KB)
// ---------------------------------------------------------------------------

template <int L>
__device__ __forceinline__ void mix_one(const float* __restrict__ Ws,
                                        const float* __restrict__ dens,
                                        float* __restrict__ dst,
                                        int n0, int q, int h) {
    constexpr int d = 2 * L + 1, mo = L * L;
    float acc[8][d];
#pragma unroll
    for (int p = 0; p < 8; ++p)
#pragma unroll
        for (int m = 0; m < d; ++m) acc[p][m] = 0.f;

#pragma unroll 4
    for (int k = 0; k < 128; ++k) {
        float w = Ws[k * 128 + q];
#pragma unroll
        for (int p = 0; p < 8; ++p)
#pragma unroll
            for (int m = 0; m < d; ++m)
                acc[p][m] += dens[((h * 8 + p) * 16 + mo + m) * 128 + k] * w;
    }
#pragma unroll
    for (int p = 0; p < 8; ++p)
#pragma unroll
        for (int m = 0; m < d; ++m) {
            int gi = NPTS * 128 * mo + ((n0 + h * 8 + p) * d + m) * 128 + q;
            dst[gi] = acc[p][m];
        }
}

__global__ __launch_bounds__(256) void mix_kernel(
    const float* __restrict__ f0, const float* __restrict__ f1,
    const float* __restrict__ f2, const float* __restrict__ f3,
    const float* __restrict__ mixer_w, float* __restrict__ out)
{
    extern __shared__ float sm[];
    float* dens = sm;          // 32768 floats
    float* Ws   = sm + 32768;  // 16384 floats

    const int tid = threadIdx.x;
    const int n0  = blockIdx.x * 16;

    // stage density for 16 points (all 16 m-components)
    for (int idx = tid; idx < 32768; idx += 256) {
        int p  = idx >> 11;
        int gm = (idx >> 7) & 15;
        int k  = idx & 127;
        int l  = (gm >= 9) ? 3 : (gm >= 4) ? 2 : (gm >= 1) ? 1 : 0;
        int lm = gm - l * l;
        const float* fp = (l == 0) ? f0 : (l == 1) ? f1 : (l == 2) ? f2 : f3;
        dens[idx] = fp[((n0 + p) * (2 * l + 1) + lm) * 128 + k];
    }

    const int q = tid & 127, h = tid >> 7;

    for (int i = 0; i < 3; ++i) {
        float* dst = (i == 0) ? out : ((i == 1) ? g_m1 : g_m2);

#define MIX_L(L)                                                              \
        {                                                                     \
            __syncthreads();                                                  \
            const float* W = mixer_w + (i * 4 + L) * 16384;                   \
            for (int idx = tid; idx < 16384; idx += 256) Ws[idx] = W[idx];    \
            __syncthreads();                                                  \
            mix_one<L>(Ws, dens, dst, n0, q, h);                              \
        }
        MIX_L(0) MIX_L(1) MIX_L(2) MIX_L(3)
#undef MIX_L
    }
}

// ---------------------------------------------------------------------------
// tp kernel: tp = TP(current, mixed_b, cg); current += tp @ iter_w
// Block = 8 points, 256 threads (2 groups of 128; thread = channel).
// SMEM: cg[21952] + tp[8][16][128] + Ws[128][128]  = 218880 bytes
// ---------------------------------------------------------------------------

template <int L>
__device__ __forceinline__ void lin_one(const float* __restrict__ Ws,
                                        const float* __restrict__ tp_s,
                                        float* __restrict__ cur,
                                        int n0, int q, int h) {
    constexpr int d = 2 * L + 1, mo = L * L;
    float acc[4][d];
#pragma unroll
    for (int p = 0; p < 4; ++p)
#pragma unroll
        for (int m = 0; m < d; ++m) acc[p][m] = 0.f;

#pragma unroll 4
    for (int k = 0; k < 128; ++k) {
        float w = Ws[k * 128 + q];
#pragma unroll
        for (int p = 0; p < 4; ++p)
#pragma unroll
            for (int m = 0; m < d; ++m)
                acc[p][m] += tp_s[((h * 4 + p) * 16 + mo + m) * 128 + k] * w;
    }
#pragma unroll
    for (int p = 0; p < 4; ++p)
#pragma unroll
        for (int m = 0; m < d; ++m) {
            int gi = NPTS * 128 * mo + ((n0 + h * 4 + p) * d + m) * 128 + q;
            cur[gi] += acc[p][m];
        }
}

__global__ __launch_bounds__(256) void tp_kernel(
    float* __restrict__ cur,            // d_out, updated in place
    const float* __restrict__ iter_w,   // pre-offset for this iteration: [4][128][128]
    const float* __restrict__ cg,       // [4][4][4][7][7][7]
    int which)                          // 0 -> g_m1, 1 -> g_m2
{
    extern __shared__ float sm[];
    float* cg_s = sm;                   // 21952
    float* tp_s = sm + 21952;           // 16384
    float* Ws   = sm + 21952 + 16384;   // 16384

    const float* __restrict__ bbuf = which ? g_m2 : g_m1;
    const int tid = threadIdx.x;

    for (int idx = tid; idx < 21952; idx += 256) cg_s[idx] = cg[idx];
    __syncthreads();

    const int q = tid & 127, h = tid >> 7;
    const int n0 = blockIdx.x * 8;

    // --- tensor product phase: each half handles 4 points sequentially ---
    for (int pp = 0; pp < 4; ++pp) {
        const int p = h * 4 + pp;
        const int n = n0 + p;

        float a[16], b[16], t[16];
#pragma unroll
        for (int l = 0; l < 4; ++l) {
            const int d = 2 * l + 1, mo = l * l;
#pragma unroll
            for (int m = 0; m < d; ++m) {
                int gi = NPTS * 128 * mo + (n * d + m) * 128 + q;
                a[mo + m] = cur[gi];
                b[mo + m] = bbuf[gi];
            }
        }
#pragma unroll
        for (int x = 0; x < 16; ++x) t[x] = 0.f;

        // fully-unrolled CG contraction over valid (l1,l2,l) triples
#define TP_PAIR(L1, L2)                                                        \
        {                                                                      \
            _Pragma("unroll")                                                  \
            for (int i = 0; i < 2 * L1 + 1; ++i) {                             \
                _Pragma("unroll")                                              \
                for (int j = 0; j < 2 * L2 + 1; ++j) {                         \
                    float pr = a[L1 * L1 + i] * b[L2 * L2 + j];                \
                    _Pragma("unroll")                                          \
                    for (int l = (L1 > L2 ? L1 - L2 : L2 - L1);                \
                         l <= (L1 + L2 < 3 ? L1 + L2 : 3); ++l) {              \
                        _Pragma("unroll")                                      \
                        for (int m = 0; m < 2 * l + 1; ++m)                    \
                            t[l * l + m] +=                                    \
                                cg_s[((((L1 * 4 + L2) * 4 + l) * 7 + i) * 7    \
                                      + j) * 7 + m] * pr;                      \
                    }                                                          \
                }                                                              \
            }                                                                  \
        }
        TP_PAIR(0,0) TP_PAIR(0,1) TP_PAIR(0,2) TP_PAIR(0,3)
        TP_PAIR(1,0) TP_PAIR(1,1) TP_PAIR(1,2) TP_PAIR(1,3)
        TP_PAIR(2,0) TP_PAIR(2,1) TP_PAIR(2,2) TP_PAIR(2,3)
        TP_PAIR(3,0) TP_PAIR(3,1) TP_PAIR(3,2) TP_PAIR(3,3)
#undef TP_PAIR

#pragma unroll
        for (int x = 0; x < 16; ++x) tp_s[(p * 16 + x) * 128 + q] = t[x];
    }

    // --- linear + residual-add phase ---
#define LIN_L(L)                                                               \
    {                                                                          \
        __syncthreads();                                                       \
        for (int idx = tid; idx < 16384; idx += 256)                           \
            Ws[idx] = iter_w[L * 16384 + idx];                                 \
        __syncthreads();                                                       \
        lin_one<L>(Ws, tp_s, cur, n0, q, h);                                   \
    }
    LIN_L(0) LIN_L(1) LIN_L(2) LIN_L(3)
#undef LIN_L
}

// ---------------------------------------------------------------------------

extern "C" void kernel_launch(void* const* d_in, const int* in_sizes, int n_in,
                              void* d_out, int out_size) {
    const float* f0      = (const float*)d_in[0];
    const float* f1      = (const float*)d_in[1];
    const float* f2      = (const float*)d_in[2];
    const float* f3      = (const float*)d_in[3];
    const float* mixer_w = (const float*)d_in[4];
    const float* iter_w  = (const float*)d_in[5];
    const float* cg      = (const float*)d_in[6];
    float* out = (float*)d_out;

    cudaFuncSetAttribute(mix_kernel, cudaFuncAttributeMaxDynamicSharedMemorySize,
                         (32768 + 16384) * 4);
    cudaFuncSetAttribute(tp_kernel, cudaFuncAttributeMaxDynamicSharedMemorySize,
                         (21952 + 16384 + 16384) * 4);

    mix_kernel<<<NPTS / 16, 256, (32768 + 16384) * 4>>>(f0, f1, f2, f3, mixer_w, out);
    tp_kernel<<<NPTS / 8, 256, (21952 + 16384 + 16384) * 4>>>(out, iter_w + 0 * 4 * 16384, cg, 0);
    tp_kernel<<<NPTS / 8, 256, (21952 + 16384 + 16384) * 4>>>(out, iter_w + 1 * 4 * 16384, cg, 1);
}

// round 4
// speedup vs baseline: 2.2458x; 2.2458x over previous
#include <cuda_runtime.h>

#define NPTS 16384
#define KCH  128
#define NK   (NPTS * KCH)

// Scratch (concatenated-field layout: field l at offset l*l*NK, elem (n,m,k) at
// off + (n*(2l+1)+m)*KCH + k)
__device__ float g_m1[NPTS * 16 * KCH];
__device__ float g_m2[NPTS * 16 * KCH];
__device__ float g_tp[NPTS * 16 * KCH];
__device__ float g_cgpack[3436];

// ---------------------------------------------------------------------------
// prepack: gather the 3436 valid cg entries in the exact order the TP kernel's
// unrolled contraction consumes them.
// ---------------------------------------------------------------------------
__global__ void prepack_kernel(const float* __restrict__ cg,
                               float* __restrict__ out) {
    const int tid = threadIdx.x;
    int cnt = 0;
    for (int l1 = 0; l1 < 4; ++l1)
        for (int l2 = 0; l2 < 4; ++l2)
            for (int i = 0; i < 2 * l1 + 1; ++i)
                for (int j = 0; j < 2 * l2 + 1; ++j) {
                    int lmin = (l1 > l2) ? l1 - l2 : l2 - l1;
                    int lmax = (l1 + l2 < 3) ? l1 + l2 : 3;
                    for (int l = lmin; l <= lmax; ++l)
                        for (int m = 0; m < 2 * l + 1; ++m) {
                            if ((cnt & 255) == tid)
                                out[cnt] =
                                    cg[((((l1 * 4 + l2) * 4 + l) * 7 + i) * 7 + j) * 7 + m];
                            ++cnt;
                        }
                }
}

// ---------------------------------------------------------------------------
// gemm: C[l] (+)= A[l] @ W[i][l] for a 128x128 output tile.
// 256 threads, 8x8 micro-tile/thread. Dyn smem: Ws[128*128] + As[128*36].
// Grid: i-major (2048 blocks per dst), l-segments [128,384,640,896] tiles.
// ---------------------------------------------------------------------------
#define GEMM_SMEM ((128 * 128 + 128 * 36) * 4)

__global__ __launch_bounds__(256) void gemm_kernel(
    const float* __restrict__ A0, const float* __restrict__ A1,
    const float* __restrict__ A2, const float* __restrict__ A3,
    float* __restrict__ C0, float* __restrict__ C1, float* __restrict__ C2,
    const float* __restrict__ W, int add)
{
    extern __shared__ float sm[];
    float* Ws = sm;              // [128][128]
    float* As = sm + 16384;      // [128][36]

    const int bid = blockIdx.x;
    const int i = bid >> 11;
    const int r = bid & 2047;
    int l, t;
    if (r < 128)       { l = 0; t = r; }
    else if (r < 512)  { l = 1; t = r - 128; }
    else if (r < 1152) { l = 2; t = r - 512; }
    else               { l = 3; t = r - 1152; }

    const float* __restrict__ A = (l == 0) ? A0 : (l == 1) ? A1 : (l == 2) ? A2 : A3;
    float* __restrict__ C = ((i == 0) ? C0 : (i == 1) ? C1 : C2) + l * l * NK;
    const float* __restrict__ Wp = W + (i * 4 + l) * 16384;
    const int row0 = t * 128;

    const int tid = threadIdx.x;

    // stage full W (16384 floats)
#pragma unroll
    for (int j = 0; j < 16; ++j) {
        int idx = (tid + j * 256) * 4;
        *(float4*)&Ws[idx] = *(const float4*)&Wp[idx];
    }

    const float* __restrict__ Ab = A + row0 * 128;

    float acc[8][8];
#pragma unroll
    for (int a = 0; a < 8; ++a)
#pragma unroll
        for (int b = 0; b < 8; ++b) acc[a][b] = 0.f;

    const int tx = tid & 15, ty = tid >> 4;
    const int r0 = ty * 8, q0 = tx * 8;

    for (int kc = 0; kc < 128; kc += 32) {
        __syncthreads();
        // stage A tile [128 rows][32 k] -> As[r][k] (stride 36)
#pragma unroll
        for (int j = 0; j < 4; ++j) {
            int id = tid + j * 256;
            int rr = id >> 3, kg = (id & 7) * 4;
            float4 v = *(const float4*)&Ab[rr * 128 + kc + kg];
            *(float4*)&As[rr * 36 + kg] = v;
        }
        __syncthreads();

#pragma unroll
        for (int k = 0; k < 32; ++k) {
            float4 blo = *(const float4*)&Ws[(kc + k) * 128 + q0];
            float4 bhi = *(const float4*)&Ws[(kc + k) * 128 + q0 + 4];
            float av[8];
#pragma unroll
            for (int ii = 0; ii < 8; ++ii) av[ii] = As[(r0 + ii) * 36 + k];
#pragma unroll
            for (int ii = 0; ii < 8; ++ii) {
                acc[ii][0] += av[ii] * blo.x;
                acc[ii][1] += av[ii] * blo.y;
                acc[ii][2] += av[ii] * blo.z;
                acc[ii][3] += av[ii] * blo.w;
                acc[ii][4] += av[ii] * bhi.x;
                acc[ii][5] += av[ii] * bhi.y;
                acc[ii][6] += av[ii] * bhi.z;
                acc[ii][7] += av[ii] * bhi.w;
            }
        }
    }

#pragma unroll
    for (int ii = 0; ii < 8; ++ii) {
        float* cp = &C[(row0 + r0 + ii) * 128 + q0];
        float4 v0 = make_float4(acc[ii][0], acc[ii][1], acc[ii][2], acc[ii][3]);
        float4 v1 = make_float4(acc[ii][4], acc[ii][5], acc[ii][6], acc[ii][7]);
        if (add) {
            float4 o0 = *(const float4*)&cp[0];
            float4 o1 = *(const float4*)&cp[4];
            v0.x += o0.x; v0.y += o0.y; v0.z += o0.z; v0.w += o0.w;
            v1.x += o1.x; v1.y += o1.y; v1.z += o1.z; v1.w += o1.w;
        }
        *(float4*)&cp[0] = v0;
        *(float4*)&cp[4] = v1;
    }
}

// ---------------------------------------------------------------------------
// tp: tp_out = TP(cur, mixed, cg). 128 threads (thread = channel q),
// 2 points per thread so each cg LDS feeds 2 FMAs. Packed cg in smem.
// ---------------------------------------------------------------------------
__global__ __launch_bounds__(128, 3) void tp_kernel(
    const float* __restrict__ cur, const float* __restrict__ mixed,
    const float* __restrict__ cgp_g, float* __restrict__ tp_out)
{
    __shared__ float cgp[3436];
    const int tid = threadIdx.x;
    for (int idx = tid; idx < 3436; idx += 128) cgp[idx] = cgp_g[idx];
    __syncthreads();

    const int q = tid;
    const int n0 = blockIdx.x * 2;

    float a0[16], a1[16], b0[16], b1[16], t0[16], t1[16];
#pragma unroll
    for (int l = 0; l < 4; ++l) {
        const int d = 2 * l + 1, mo = l * l;
#pragma unroll
        for (int m = 0; m < d; ++m) {
            int gi0 = l * l * NK + ((n0 + 0) * d + m) * 128 + q;
            int gi1 = l * l * NK + ((n0 + 1) * d + m) * 128 + q;
            a0[mo + m] = cur[gi0];   a1[mo + m] = cur[gi1];
            b0[mo + m] = mixed[gi0]; b1[mo + m] = mixed[gi1];
        }
    }
#pragma unroll
    for (int x = 0; x < 16; ++x) { t0[x] = 0.f; t1[x] = 0.f; }

    int cnt = 0;
#define TP_PAIR(L1, L2)                                                        \
    {                                                                          \
        _Pragma("unroll")                                                      \
        for (int i = 0; i < 2 * L1 + 1; ++i) {                                 \
            _Pragma("unroll")                                                  \
            for (int j = 0; j < 2 * L2 + 1; ++j) {                             \
                float pr0 = a0[L1 * L1 + i] * b0[L2 * L2 + j];                 \
                float pr1 = a1[L1 * L1 + i] * b1[L2 * L2 + j];                 \
                _Pragma("unroll")                                              \
                for (int l = (L1 > L2 ? L1 - L2 : L2 - L1);                    \
                     l <= (L1 + L2 < 3 ? L1 + L2 : 3); ++l) {                  \
                    _Pragma("unroll")                                          \
                    for (int m = 0; m < 2 * l + 1; ++m) {                      \
                        float c = cgp[cnt];                                    \
                        t0[l * l + m] += c * pr0;                              \
                        t1[l * l + m] += c * pr1;                              \
                        ++cnt;                                                 \
                    }                                                          \
                }                                                              \
            }                                                                  \
        }                                                                      \
    }
    TP_PAIR(0,0) TP_PAIR(0,1) TP_PAIR(0,2) TP_PAIR(0,3)
    TP_PAIR(1,0) TP_PAIR(1,1) TP_PAIR(1,2) TP_PAIR(1,3)
    TP_PAIR(2,0) TP_PAIR(2,1) TP_PAIR(2,2) TP_PAIR(2,3)
    TP_PAIR(3,0) TP_PAIR(3,1) TP_PAIR(3,2) TP_PAIR(3,3)
#undef TP_PAIR

#pragma unroll
    for (int l = 0; l < 4; ++l) {
        const int d = 2 * l + 1, mo = l * l;
#pragma unroll
        for (int m = 0; m < d; ++m) {
            tp_out[l * l * NK + ((n0 + 0) * d + m) * 128 + q] = t0[mo + m];
            tp_out[l * l * NK + ((n0 + 1) * d + m) * 128 + q] = t1[mo + m];
        }
    }
}

// ---------------------------------------------------------------------------

extern "C" void kernel_launch(void* const* d_in, const int* in_sizes, int n_in,
                              void* d_out, int out_size) {
    const float* f0      = (const float*)d_in[0];
    const float* f1      = (const float*)d_in[1];
    const float* f2      = (const float*)d_in[2];
    const float* f3      = (const float*)d_in[3];
    const float* mixer_w = (const float*)d_in[4];
    const float* iter_w  = (const float*)d_in[5];
    const float* cg      = (const float*)d_in[6];
    float* out = (float*)d_out;

    float *m1p, *m2p, *tpp, *cgpp;
    cudaGetSymbolAddress((void**)&m1p, g_m1);
    cudaGetSymbolAddress((void**)&m2p, g_m2);
    cudaGetSymbolAddress((void**)&tpp, g_tp);
    cudaGetSymbolAddress((void**)&cgpp, g_cgpack);

    cudaFuncSetAttribute(gemm_kernel,
                         cudaFuncAttributeMaxDynamicSharedMemorySize, GEMM_SMEM);

    prepack_kernel<<<1, 256>>>(cg, cgpp);

    // mixed0 -> out, mixed1 -> g_m1, mixed2 -> g_m2   (3 * 2048 blocks)
    gemm_kernel<<<6144, 256, GEMM_SMEM>>>(f0, f1, f2, f3,
                                          out, m1p, m2p, mixer_w, 0);

    // iteration 0
    tp_kernel<<<NPTS / 2, 128>>>(out, m1p, cgpp, tpp);
    gemm_kernel<<<2048, 256, GEMM_SMEM>>>(tpp, tpp + NK, tpp + 4 * NK, tpp + 9 * NK,
                                          out, out, out, iter_w + 0 * 4 * 16384, 1);

    // iteration 1
    tp_kernel<<<NPTS / 2, 128>>>(out, m2p, cgpp, tpp);
    gemm_kernel<<<2048, 256, GEMM_SMEM>>>(tpp, tpp + NK, tpp + 4 * NK, tpp + 9 * NK,
                                          out, out, out, iter_w + 1 * 4 * 16384, 1);
}